// round 2
// baseline (speedup 1.0000x reference)
#include <cuda_runtime.h>
#include <math.h>

// ---------------------------------------------------------------------------
// FreeYOLOv2 post-process:
//   3 levels: cls [1,80,H,W], reg [1,64,H,W], strides 8/16/32
//   per level: top-1000 of sigmoid(cls) flattened as (m*C + c)
//              DFL: dist = softmax(reg[m,f,:]) . proj ; boxes from anchors
//   concat -> stable sort by score desc -> class-shifted greedy NMS (0.6)
//   outputs: bboxes[3000,4], scores*keep[3000], labels[3000], keep[3000]
// ---------------------------------------------------------------------------

#define NBINS    8192
#define CAND_CAP 4096
#define NSEL     1000
#define NTOT     3000

__device__ unsigned int       g_hist[3][NBINS];
__device__ unsigned int       g_candCnt[3];
__device__ unsigned int       g_cutKey[3];
__device__ unsigned long long g_cand[3][CAND_CAP];

__device__ float  g_selScore[NTOT];
__device__ int    g_selLabel[NTOT];
__device__ float4 g_selBox[NTOT];

__device__ float  g_sScore[NTOT];
__device__ int    g_sLabel[NTOT];
__device__ float4 g_sBox[NTOT];
__device__ float4 g_sShift[NTOT];
__device__ unsigned char g_keep[NTOT];

// monotone uint key for float ordering
__device__ __forceinline__ unsigned int fkey(float x) {
    unsigned int u = __float_as_uint(x);
    return (u & 0x80000000u) ? ~u : (u | 0x80000000u);
}

struct Lev { int C, H, W, M, n, logM; float stride; };
__device__ __forceinline__ Lev lev_params(int l) {
    Lev p; p.C = 80;
    if (l == 0)      { p.H = 512; p.W = 512; p.stride = 8.f;  p.logM = 18; }
    else if (l == 1) { p.H = 256; p.W = 256; p.stride = 16.f; p.logM = 16; }
    else             { p.H = 128; p.W = 128; p.stride = 32.f; p.logM = 14; }
    p.M = p.H * p.W; p.n = p.M * p.C;
    return p;
}

// ------------------------------- init --------------------------------------
__global__ void k_init() {
    int t = blockIdx.x * blockDim.x + threadIdx.x;
    int stride = gridDim.x * blockDim.x;
    unsigned int* h = (unsigned int*)g_hist;
    for (int i = t; i < 3 * NBINS; i += stride) h[i] = 0;
    if (t < 3) g_candCnt[t] = 0;
    for (int i = t; i < NTOT; i += stride) {
        g_selScore[i] = 0.f;
        g_selLabel[i] = 0;
        g_selBox[i]   = make_float4(0.f, 0.f, 0.f, 0.f);
    }
}

// ------------------------------ histogram ----------------------------------
__global__ void k_hist(const float* __restrict__ c0,
                       const float* __restrict__ c1,
                       const float* __restrict__ c2) {
    int l = blockIdx.y;
    Lev P = lev_params(l);
    const float4* p = (const float4*)(l == 0 ? c0 : (l == 1 ? c1 : c2));
    int n4 = P.n >> 2;
    __shared__ unsigned int h[NBINS];
    for (int i = threadIdx.x; i < NBINS; i += blockDim.x) h[i] = 0;
    __syncthreads();
    for (int i = blockIdx.x * blockDim.x + threadIdx.x; i < n4;
         i += gridDim.x * blockDim.x) {
        float4 v = p[i];
        atomicAdd(&h[fkey(v.x) >> 19], 1u);
        atomicAdd(&h[fkey(v.y) >> 19], 1u);
        atomicAdd(&h[fkey(v.z) >> 19], 1u);
        atomicAdd(&h[fkey(v.w) >> 19], 1u);
    }
    __syncthreads();
    for (int i = threadIdx.x; i < NBINS; i += blockDim.x) {
        unsigned int v = h[i];
        if (v) atomicAdd(&g_hist[l][i], v);
    }
}

// ------------------------------ cutoff -------------------------------------
// find bin b (descending) where cumulative count first reaches NSEL
__global__ void k_cutoff() {
    int l = blockIdx.x;
    __shared__ unsigned int chunk[256];
    unsigned int s = 0;
    int base = threadIdx.x * 32;
    for (int r = 0; r < 32; r++) s += g_hist[l][base + r];
    chunk[threadIdx.x] = s;
    __syncthreads();
    if (threadIdx.x == 0) {
        unsigned long long cum = 0;
        int c;
        for (c = 255; c >= 0; c--) {
            if (cum + chunk[c] >= (unsigned long long)NSEL) break;
            cum += chunk[c];
        }
        unsigned int cut = 0;
        if (c >= 0) {
            int b;
            for (b = c * 32 + 31; b >= c * 32; b--) {
                cum += g_hist[l][b];
                if (cum >= (unsigned long long)NSEL) break;
            }
            if (b < c * 32) b = c * 32;
            cut = ((unsigned int)b) << 19;
        }
        g_cutKey[l] = cut;
    }
}

// ------------------------------ compact ------------------------------------
__global__ void k_compact(const float* __restrict__ c0,
                          const float* __restrict__ c1,
                          const float* __restrict__ c2) {
    int l = blockIdx.y;
    Lev P = lev_params(l);
    const float4* p = (const float4*)(l == 0 ? c0 : (l == 1 ? c1 : c2));
    int n4 = P.n >> 2;
    unsigned int cut = g_cutKey[l];
    int Mm = P.M - 1;
    int logM = P.logM;
    for (int i = blockIdx.x * blockDim.x + threadIdx.x; i < n4;
         i += gridDim.x * blockDim.x) {
        float4 v = p[i];
        int base = i << 2;
#pragma unroll
        for (int e = 0; e < 4; e++) {
            float x = (e == 0) ? v.x : (e == 1) ? v.y : (e == 2) ? v.z : v.w;
            if (fkey(x) >= cut) {
                int lin = base + e;
                int c = lin >> logM;       // channel (class)
                int m = lin & Mm;          // spatial index
                unsigned int flat = (unsigned int)m * 80u + (unsigned int)c;
                float sc = 1.f / (1.f + expf(-x));
                unsigned long long comb =
                    ((unsigned long long)__float_as_uint(sc) << 32) |
                    (unsigned long long)(0xFFFFFFFFu - flat);
                unsigned int pos = atomicAdd(&g_candCnt[l], 1u);
                if (pos < CAND_CAP) g_cand[l][pos] = comb;
            }
        }
    }
}

// ------------------------------ bitonic ------------------------------------
template <int N>
__device__ __forceinline__ void bitonic_desc(unsigned long long* s) {
    for (int k = 2; k <= N; k <<= 1) {
        for (int j = k >> 1; j > 0; j >>= 1) {
            for (int i = threadIdx.x; i < N; i += blockDim.x) {
                int ixj = i ^ j;
                if (ixj > i) {
                    unsigned long long A = s[i], B = s[ixj];
                    bool descSeg = ((i & k) == 0);
                    if (descSeg ? (A < B) : (A > B)) { s[i] = B; s[ixj] = A; }
                }
            }
            __syncthreads();
        }
    }
}

// ------------------- per-level sort + top-1000 + decode --------------------
__global__ void k_sortsel(const float* __restrict__ r0,
                          const float* __restrict__ r1,
                          const float* __restrict__ r2,
                          const float* __restrict__ proj) {
    int l = blockIdx.x;
    Lev P = lev_params(l);
    const float* reg = (l == 0 ? r0 : (l == 1 ? r1 : r2));
    __shared__ unsigned long long a[CAND_CAP];
    __shared__ float pw[16];
    if (threadIdx.x < 16) pw[threadIdx.x] = proj[threadIdx.x];
    unsigned int cnt = g_candCnt[l];
    if (cnt > CAND_CAP) cnt = CAND_CAP;
    for (int i = threadIdx.x; i < CAND_CAP; i += blockDim.x)
        a[i] = (i < (int)cnt) ? g_cand[l][i] : 0ULL;
    __syncthreads();
    bitonic_desc<CAND_CAP>(a);

    int nsel = (int)cnt < NSEL ? (int)cnt : NSEL;
    int t = threadIdx.x;
    if (t < nsel) {
        unsigned long long e = a[t];
        float sc = __uint_as_float((unsigned int)(e >> 32));
        unsigned int flat = 0xFFFFFFFFu - (unsigned int)e;
        int m = (int)(flat / 80u);
        int c = (int)(flat % 80u);
        float dist[4];
#pragma unroll
        for (int f = 0; f < 4; f++) {
            float v[16];
            float mx = -1e30f;
#pragma unroll
            for (int r = 0; r < 16; r++) {
                v[r] = reg[(size_t)(f * 16 + r) * (size_t)P.M + (size_t)m];
                mx = fmaxf(mx, v[r]);
            }
            float s = 0.f, d = 0.f;
#pragma unroll
            for (int r = 0; r < 16; r++) {
                float ee = expf(v[r] - mx);
                s += ee;
                d += ee * pw[r];
            }
            dist[f] = d / s;
        }
        int xq = m % P.W;
        int yq = m / P.W;
        float ax = ((float)xq + 0.5f) * P.stride;
        float ay = ((float)yq + 0.5f) * P.stride;
        float4 b = make_float4(ax - dist[0] * P.stride,
                               ay - dist[1] * P.stride,
                               ax + dist[2] * P.stride,
                               ay + dist[3] * P.stride);
        int o = l * NSEL + t;
        g_selScore[o] = (sc > 0.05f) ? sc : 0.f;
        g_selLabel[o] = c;
        g_selBox[o]   = b;
    }
}

// ------------------ stable sort of 3000 by score desc ----------------------
__global__ void k_nmssort() {
    __shared__ unsigned long long a[4096];
    for (int i = threadIdx.x; i < 4096; i += blockDim.x) {
        if (i < NTOT) {
            a[i] = ((unsigned long long)__float_as_uint(g_selScore[i]) << 32) |
                   (unsigned long long)(0xFFFFFFFFu - (unsigned int)i);
        } else {
            a[i] = 0ULL;
        }
    }
    __syncthreads();
    bitonic_desc<4096>(a);
    for (int i = threadIdx.x; i < NTOT; i += blockDim.x) {
        unsigned int idx = 0xFFFFFFFFu - (unsigned int)a[i];
        float sc = g_selScore[idx];
        int lab  = g_selLabel[idx];
        float4 b = g_selBox[idx];
        g_sScore[i] = sc;
        g_sLabel[i] = lab;
        g_sBox[i]   = b;
        float off = (float)lab * 8192.0f;
        g_sShift[i] = make_float4(b.x + off, b.y + off, b.z + off, b.w + off);
    }
}

// ------------------------- greedy sequential NMS ---------------------------
__global__ void __launch_bounds__(1024, 1) k_greedy() {
    __shared__ unsigned char keep[NTOT];
    int tid = threadIdx.x;
    float4 bx[3];
    float  ar[3];
    bool   kp[3];
#pragma unroll
    for (int q = 0; q < 3; q++) {
        int j = tid + q * 1024;
        if (j < NTOT) {
            float4 b = g_sShift[j];
            bx[q] = b;
            ar[q] = (b.z - b.x) * (b.w - b.y);
            bool k0 = g_sScore[j] > 0.f;
            kp[q] = k0;
            keep[j] = k0 ? 1 : 0;
        } else {
            kp[q] = false;
        }
    }
    __syncthreads();
    for (int i = 0; i < NTOT; i++) {
        if (keep[i]) {
            float4 bi = g_sShift[i];
            float ai = (bi.z - bi.x) * (bi.w - bi.y);
#pragma unroll
            for (int q = 0; q < 3; q++) {
                int j = tid + q * 1024;
                if (kp[q] && j > i) {
                    float iw = fminf(bi.z, bx[q].z) - fmaxf(bi.x, bx[q].x);
                    iw = fmaxf(iw, 0.f);
                    float ih = fminf(bi.w, bx[q].w) - fmaxf(bi.y, bx[q].y);
                    ih = fmaxf(ih, 0.f);
                    float inter = iw * ih;
                    float iou = inter / (ai + ar[q] - inter + 1e-9f);
                    if (iou > 0.6f) { kp[q] = false; keep[j] = 0; }
                }
            }
        }
        __syncthreads();
    }
#pragma unroll
    for (int q = 0; q < 3; q++) {
        int j = tid + q * 1024;
        if (j < NTOT) g_keep[j] = kp[q] ? 1 : 0;
    }
}

// ------------------------------- output ------------------------------------
// layout guess: bboxes[3000*4] | scores*keep[3000] | labels[3000] | keep[3000]
__global__ void k_out(float* __restrict__ out, int out_size) {
    int t = blockIdx.x * blockDim.x + threadIdx.x;
    if (t >= out_size) return;
    float v = 0.f;
    if (t < 12000) {
        int r = t >> 2, c = t & 3;
        float4 b = g_sBox[r];
        v = (c == 0) ? b.x : (c == 1) ? b.y : (c == 2) ? b.z : b.w;
    } else if (t < 15000) {
        int j = t - 12000;
        v = g_keep[j] ? g_sScore[j] : 0.f;
    } else if (t < 18000) {
        int j = t - 15000;
        v = (float)g_sLabel[j];
    } else if (t < 21000) {
        int j = t - 18000;
        v = g_keep[j] ? 1.f : 0.f;
    }
    out[t] = v;
}

// ------------------------------- launch ------------------------------------
extern "C" void kernel_launch(void* const* d_in, const int* in_sizes, int n_in,
                              void* d_out, int out_size) {
    const float* cls0 = (const float*)d_in[0];
    const float* reg0 = (const float*)d_in[1];
    const float* cls1 = (const float*)d_in[2];
    const float* reg1 = (const float*)d_in[3];
    const float* cls2 = (const float*)d_in[4];
    const float* reg2 = (const float*)d_in[5];
    const float* proj = (const float*)d_in[6];
    float* out = (float*)d_out;

    k_init<<<64, 256>>>();
    dim3 g(1024, 3);
    k_hist<<<g, 256>>>(cls0, cls1, cls2);
    k_cutoff<<<3, 256>>>();
    k_compact<<<g, 256>>>(cls0, cls1, cls2);
    k_sortsel<<<3, 1024>>>(reg0, reg1, reg2, proj);
    k_nmssort<<<1, 1024>>>();
    k_greedy<<<1, 1024>>>();
    int nb = (out_size + 255) / 256;
    if (nb < 1) nb = 1;
    k_out<<<nb, 256>>>(out, out_size);
}

// round 3
// speedup vs baseline: 4.4013x; 4.4013x over previous
#include <cuda_runtime.h>
#include <math.h>

// ---------------------------------------------------------------------------
// FreeYOLOv2 post-process:
//   3 levels: cls [1,80,H,W], reg [1,64,H,W], strides 8/16/32
//   per level: top-1000 of sigmoid(cls) flattened as (m*C + c)
//              DFL: dist = softmax(reg[m,f,:]) . proj ; boxes from anchors
//   concat -> stable sort by score desc -> class-shifted greedy NMS (0.6)
//   outputs: bboxes[3000,4], scores*keep[3000], labels[3000], keep[3000]
// ---------------------------------------------------------------------------

#define NBINS    8192
#define CAND_CAP 4096
#define NSEL     1000
#define NTOT     3000
#define NW32     96     // ceil(3000/32)
#define NWPAD    128    // padded words per mask row (uint4 per lane, 32 lanes)

__device__ unsigned int       g_hist[3][NBINS];
__device__ unsigned int       g_candCnt[3];
__device__ unsigned int       g_cutKey[3];
__device__ unsigned long long g_cand[3][CAND_CAP];

__device__ float  g_selScore[NTOT];
__device__ int    g_selLabel[NTOT];
__device__ float4 g_selBox[NTOT];

__device__ float  g_sScore[NTOT];
__device__ int    g_sLabel[NTOT];
__device__ float4 g_sBox[NTOT];
__device__ float4 g_sShift[NTOT];

__device__ uint4  g_aliveV[32];            // 128 words (96 used) initial keep bits
__device__ uint4  g_maskV[NTOT * 32];      // suppression matrix rows, 128 words/row
__device__ uint4  g_keepV[32];             // final keep bits

// monotone uint key for float ordering
__device__ __forceinline__ unsigned int fkey(float x) {
    unsigned int u = __float_as_uint(x);
    return (u & 0x80000000u) ? ~u : (u | 0x80000000u);
}

struct Lev { int C, H, W, M, n, logM; float stride; };
__device__ __forceinline__ Lev lev_params(int l) {
    Lev p; p.C = 80;
    if (l == 0)      { p.H = 512; p.W = 512; p.stride = 8.f;  p.logM = 18; }
    else if (l == 1) { p.H = 256; p.W = 256; p.stride = 16.f; p.logM = 16; }
    else             { p.H = 128; p.W = 128; p.stride = 32.f; p.logM = 14; }
    p.M = p.H * p.W; p.n = p.M * p.C;
    return p;
}

// ------------------------------- init --------------------------------------
__global__ void k_init() {
    int t = blockIdx.x * blockDim.x + threadIdx.x;
    int stride = gridDim.x * blockDim.x;
    unsigned int* h = (unsigned int*)g_hist;
    for (int i = t; i < 3 * NBINS; i += stride) h[i] = 0;
    if (t < 3) g_candCnt[t] = 0;
    for (int i = t; i < NTOT; i += stride) {
        g_selScore[i] = 0.f;
        g_selLabel[i] = 0;
        g_selBox[i]   = make_float4(0.f, 0.f, 0.f, 0.f);
    }
}

// ------------------------------ histogram ----------------------------------
__global__ void k_hist(const float* __restrict__ c0,
                       const float* __restrict__ c1,
                       const float* __restrict__ c2) {
    int l = blockIdx.y;
    Lev P = lev_params(l);
    const float4* p = (const float4*)(l == 0 ? c0 : (l == 1 ? c1 : c2));
    int n4 = P.n >> 2;
    __shared__ unsigned int h[NBINS];
    for (int i = threadIdx.x; i < NBINS; i += blockDim.x) h[i] = 0;
    __syncthreads();
    for (int i = blockIdx.x * blockDim.x + threadIdx.x; i < n4;
         i += gridDim.x * blockDim.x) {
        float4 v = p[i];
        atomicAdd(&h[fkey(v.x) >> 19], 1u);
        atomicAdd(&h[fkey(v.y) >> 19], 1u);
        atomicAdd(&h[fkey(v.z) >> 19], 1u);
        atomicAdd(&h[fkey(v.w) >> 19], 1u);
    }
    __syncthreads();
    for (int i = threadIdx.x; i < NBINS; i += blockDim.x) {
        unsigned int v = h[i];
        if (v) atomicAdd(&g_hist[l][i], v);
    }
}

// ------------------------------ cutoff -------------------------------------
__global__ void k_cutoff() {
    int l = blockIdx.x;
    __shared__ unsigned int chunk[256];
    unsigned int s = 0;
    int base = threadIdx.x * 32;
    for (int r = 0; r < 32; r++) s += g_hist[l][base + r];
    chunk[threadIdx.x] = s;
    __syncthreads();
    if (threadIdx.x == 0) {
        unsigned long long cum = 0;
        int c;
        for (c = 255; c >= 0; c--) {
            if (cum + chunk[c] >= (unsigned long long)NSEL) break;
            cum += chunk[c];
        }
        unsigned int cut = 0;
        if (c >= 0) {
            int b;
            for (b = c * 32 + 31; b >= c * 32; b--) {
                cum += g_hist[l][b];
                if (cum >= (unsigned long long)NSEL) break;
            }
            if (b < c * 32) b = c * 32;
            cut = ((unsigned int)b) << 19;
        }
        g_cutKey[l] = cut;
    }
}

// ------------------------------ compact ------------------------------------
__global__ void k_compact(const float* __restrict__ c0,
                          const float* __restrict__ c1,
                          const float* __restrict__ c2) {
    int l = blockIdx.y;
    Lev P = lev_params(l);
    const float4* p = (const float4*)(l == 0 ? c0 : (l == 1 ? c1 : c2));
    int n4 = P.n >> 2;
    unsigned int cut = g_cutKey[l];
    int Mm = P.M - 1;
    int logM = P.logM;
    for (int i = blockIdx.x * blockDim.x + threadIdx.x; i < n4;
         i += gridDim.x * blockDim.x) {
        float4 v = p[i];
        int base = i << 2;
#pragma unroll
        for (int e = 0; e < 4; e++) {
            float x = (e == 0) ? v.x : (e == 1) ? v.y : (e == 2) ? v.z : v.w;
            if (fkey(x) >= cut) {
                int lin = base + e;
                int c = lin >> logM;
                int m = lin & Mm;
                unsigned int flat = (unsigned int)m * 80u + (unsigned int)c;
                float sc = 1.f / (1.f + expf(-x));
                unsigned long long comb =
                    ((unsigned long long)__float_as_uint(sc) << 32) |
                    (unsigned long long)(0xFFFFFFFFu - flat);
                unsigned int pos = atomicAdd(&g_candCnt[l], 1u);
                if (pos < CAND_CAP) g_cand[l][pos] = comb;
            }
        }
    }
}

// ------------------------------ bitonic ------------------------------------
template <int N>
__device__ __forceinline__ void bitonic_desc(unsigned long long* s) {
    for (int k = 2; k <= N; k <<= 1) {
        for (int j = k >> 1; j > 0; j >>= 1) {
            for (int i = threadIdx.x; i < N; i += blockDim.x) {
                int ixj = i ^ j;
                if (ixj > i) {
                    unsigned long long A = s[i], B = s[ixj];
                    bool descSeg = ((i & k) == 0);
                    if (descSeg ? (A < B) : (A > B)) { s[i] = B; s[ixj] = A; }
                }
            }
            __syncthreads();
        }
    }
}

// ------------------- per-level sort + top-1000 + decode --------------------
__global__ void k_sortsel(const float* __restrict__ r0,
                          const float* __restrict__ r1,
                          const float* __restrict__ r2,
                          const float* __restrict__ proj) {
    int l = blockIdx.x;
    Lev P = lev_params(l);
    const float* reg = (l == 0 ? r0 : (l == 1 ? r1 : r2));
    __shared__ unsigned long long a[CAND_CAP];
    __shared__ float pw[16];
    if (threadIdx.x < 16) pw[threadIdx.x] = proj[threadIdx.x];
    unsigned int cnt = g_candCnt[l];
    if (cnt > CAND_CAP) cnt = CAND_CAP;
    for (int i = threadIdx.x; i < CAND_CAP; i += blockDim.x)
        a[i] = (i < (int)cnt) ? g_cand[l][i] : 0ULL;
    __syncthreads();
    bitonic_desc<CAND_CAP>(a);

    int nsel = (int)cnt < NSEL ? (int)cnt : NSEL;
    int t = threadIdx.x;
    if (t < nsel) {
        unsigned long long e = a[t];
        float sc = __uint_as_float((unsigned int)(e >> 32));
        unsigned int flat = 0xFFFFFFFFu - (unsigned int)e;
        int m = (int)(flat / 80u);
        int c = (int)(flat % 80u);
        float dist[4];
#pragma unroll
        for (int f = 0; f < 4; f++) {
            float v[16];
            float mx = -1e30f;
#pragma unroll
            for (int r = 0; r < 16; r++) {
                v[r] = reg[(size_t)(f * 16 + r) * (size_t)P.M + (size_t)m];
                mx = fmaxf(mx, v[r]);
            }
            float s = 0.f, d = 0.f;
#pragma unroll
            for (int r = 0; r < 16; r++) {
                float ee = expf(v[r] - mx);
                s += ee;
                d += ee * pw[r];
            }
            dist[f] = d / s;
        }
        int xq = m % P.W;
        int yq = m / P.W;
        float ax = ((float)xq + 0.5f) * P.stride;
        float ay = ((float)yq + 0.5f) * P.stride;
        float4 b = make_float4(ax - dist[0] * P.stride,
                               ay - dist[1] * P.stride,
                               ax + dist[2] * P.stride,
                               ay + dist[3] * P.stride);
        int o = l * NSEL + t;
        g_selScore[o] = (sc > 0.05f) ? sc : 0.f;
        g_selLabel[o] = c;
        g_selBox[o]   = b;
    }
}

// ------------------ stable sort of 3000 by score desc ----------------------
// also emits initial alive bitset (score > 0) for the mask-NMS reduce.
__global__ void k_nmssort() {
    __shared__ unsigned long long a[4096];
    for (int i = threadIdx.x; i < 4096; i += blockDim.x) {
        if (i < NTOT) {
            a[i] = ((unsigned long long)__float_as_uint(g_selScore[i]) << 32) |
                   (unsigned long long)(0xFFFFFFFFu - (unsigned int)i);
        } else {
            a[i] = 0ULL;
        }
    }
    __syncthreads();
    bitonic_desc<4096>(a);
    unsigned int* aliveW = (unsigned int*)g_aliveV;
#pragma unroll
    for (int p = 0; p < 3; p++) {
        int i = p * 1024 + threadIdx.x;   // sorted slot
        bool al = false;
        if (i < NTOT) {
            unsigned int idx = 0xFFFFFFFFu - (unsigned int)a[i];
            float sc = g_selScore[idx];
            int lab  = g_selLabel[idx];
            float4 b = g_selBox[idx];
            g_sScore[i] = sc;
            g_sLabel[i] = lab;
            g_sBox[i]   = b;
            float off = (float)lab * 8192.0f;
            g_sShift[i] = make_float4(b.x + off, b.y + off, b.z + off, b.w + off);
            al = sc > 0.f;
        }
        unsigned int bal = __ballot_sync(0xFFFFFFFFu, al);
        if ((threadIdx.x & 31) == 0) aliveW[i >> 5] = bal;
    }
    if (threadIdx.x < 32) aliveW[NW32 + threadIdx.x] = 0u;  // pad 96..127
}

// --------------------- suppression bitmask matrix --------------------------
// One warp per row i. Word k (k<96) covers j in [32k, 32k+31]; bit set iff
// j > i && iou(shift_i, shift_j) > 0.6. Padded to 128 words (uint4/lane).
__global__ void __launch_bounds__(256) k_iou() {
    __shared__ float4 sb[NTOT];
    for (int i = threadIdx.x; i < NTOT; i += blockDim.x) sb[i] = g_sShift[i];
    __syncthreads();

    int row  = blockIdx.x * 8 + (threadIdx.x >> 5);
    int lane = threadIdx.x & 31;
    if (row >= NTOT) return;

    float4 bi = sb[row];
    float ai = (bi.z - bi.x) * (bi.w - bi.y);

    uint4 v = make_uint4(0u, 0u, 0u, 0u);
#pragma unroll
    for (int k = 0; k < NW32; k++) {
        int j = k * 32 + lane;
        bool pred = false;
        if (j < NTOT && j > row) {
            float4 bj = sb[j];
            float aj = (bj.z - bj.x) * (bj.w - bj.y);
            float iw = fminf(bi.z, bj.z) - fmaxf(bi.x, bj.x);
            iw = fmaxf(iw, 0.f);
            float ih = fminf(bi.w, bj.w) - fmaxf(bi.y, bj.y);
            ih = fmaxf(ih, 0.f);
            float inter = iw * ih;
            float iou = inter / (ai + aj - inter + 1e-9f);
            pred = iou > 0.6f;
        }
        unsigned int bal = __ballot_sync(0xFFFFFFFFu, pred);
        if (lane == (k >> 2)) {
            if ((k & 3) == 0)      v.x = bal;
            else if ((k & 3) == 1) v.y = bal;
            else if ((k & 3) == 2) v.z = bal;
            else                   v.w = bal;
        }
    }
    g_maskV[row * 32 + lane] = v;
}

// ------------------------- greedy mask reduce ------------------------------
// Single warp, no block barriers. alive bitset in registers (uint4/lane =
// words lane*4..lane*4+3). Sequential: if alive(i): alive &= ~row(i).
// Rolling register prefetch (depth PD) hides L2 latency; each row's own
// current-region word is loaded as a uniform scalar so the cached 'cur'
// word updates with an AND (no shuffle on the critical chain).
#define PD 16
__global__ void __launch_bounds__(32) k_reduce() {
    int lane = threadIdx.x;
    uint4 A = g_aliveV[lane];
    const uint4* mv = (const uint4*)g_maskV;
    const unsigned int* mw = (const unsigned int*)g_maskV;

    uint4 buf[PD];
    unsigned int bufw[PD];
#pragma unroll
    for (int j = 0; j < PD; j++) {
        if (j < NTOT) {
            buf[j]  = mv[j * 32 + lane];
            bufw[j] = mw[j * NWPAD + (j >> 5)];
        } else { buf[j] = make_uint4(0u,0u,0u,0u); bufw[j] = 0u; }
    }

    unsigned int cur = 0;
    int curw = -1;
    for (int base = 0; base < NTOT; base += PD) {
#pragma unroll
        for (int j = 0; j < PD; j++) {
            int i = base + j;
            if (i < NTOT) {
                int w = i >> 5;
                if (w != curw) {
                    int sel = w & 3;
                    unsigned int val = (sel == 0) ? A.x :
                                       (sel == 1) ? A.y :
                                       (sel == 2) ? A.z : A.w;
                    cur = __shfl_sync(0xFFFFFFFFu, val, w >> 2);
                    curw = w;
                }
                if ((cur >> (i & 31)) & 1u) {
                    A.x &= ~buf[j].x;
                    A.y &= ~buf[j].y;
                    A.z &= ~buf[j].z;
                    A.w &= ~buf[j].w;
                    cur &= ~bufw[j];
                }
            }
            int nx = base + j + PD;
            if (nx < NTOT) {
                buf[j]  = mv[nx * 32 + lane];
                bufw[j] = mw[nx * NWPAD + (nx >> 5)];
            } else { buf[j] = make_uint4(0u,0u,0u,0u); bufw[j] = 0u; }
        }
    }
    g_keepV[lane] = A;
}

// ------------------------------- output ------------------------------------
// layout: bboxes[3000*4] | scores*keep[3000] | labels[3000] | keep[3000]
__global__ void k_out(float* __restrict__ out, int out_size) {
    int t = blockIdx.x * blockDim.x + threadIdx.x;
    if (t >= out_size) return;
    const unsigned int* kw = (const unsigned int*)g_keepV;
    float v = 0.f;
    if (t < 12000) {
        int r = t >> 2, c = t & 3;
        float4 b = g_sBox[r];
        v = (c == 0) ? b.x : (c == 1) ? b.y : (c == 2) ? b.z : b.w;
    } else if (t < 15000) {
        int j = t - 12000;
        bool kp = (kw[j >> 5] >> (j & 31)) & 1u;
        v = kp ? g_sScore[j] : 0.f;
    } else if (t < 18000) {
        int j = t - 15000;
        v = (float)g_sLabel[j];
    } else if (t < 21000) {
        int j = t - 18000;
        v = ((kw[j >> 5] >> (j & 31)) & 1u) ? 1.f : 0.f;
    }
    out[t] = v;
}

// ------------------------------- launch ------------------------------------
extern "C" void kernel_launch(void* const* d_in, const int* in_sizes, int n_in,
                              void* d_out, int out_size) {
    const float* cls0 = (const float*)d_in[0];
    const float* reg0 = (const float*)d_in[1];
    const float* cls1 = (const float*)d_in[2];
    const float* reg1 = (const float*)d_in[3];
    const float* cls2 = (const float*)d_in[4];
    const float* reg2 = (const float*)d_in[5];
    const float* proj = (const float*)d_in[6];
    float* out = (float*)d_out;

    k_init<<<64, 256>>>();
    dim3 g(1024, 3);
    k_hist<<<g, 256>>>(cls0, cls1, cls2);
    k_cutoff<<<3, 256>>>();
    k_compact<<<g, 256>>>(cls0, cls1, cls2);
    k_sortsel<<<3, 1024>>>(reg0, reg1, reg2, proj);
    k_nmssort<<<1, 1024>>>();
    k_iou<<<(NTOT + 7) / 8, 256>>>();
    k_reduce<<<1, 32>>>();
    int nb = (out_size + 255) / 256;
    if (nb < 1) nb = 1;
    k_out<<<nb, 256>>>(out, out_size);
}

// round 4
// speedup vs baseline: 11.3735x; 2.5841x over previous
#include <cuda_runtime.h>
#include <math.h>

// ---------------------------------------------------------------------------
// FreeYOLOv2 post-process, v3:
//   one fused pass over cls (histogram + prefiltered candidate compaction),
//   exact radix-histogram cutoff with full-rescan fallback (early-exit),
//   per-level bitonic(2048/4096) top-1000 + DFL decode,
//   barrier-free 3-way merge by rank (replaces global bitonic sort),
//   IoU suppression bitmask matrix + SPARSE greedy reduce fused with output.
// ---------------------------------------------------------------------------

#define NBINS    8192
#define CAND_CAP 4096
#define NSEL     1000
#define NTOT     3000
#define NW32     96
#define NWPAD    128
#define PREKEY   0xC0333333u   /* fkey(2.8f) — static prefilter threshold */
#define CAP0     131072
#define CAP1     65536
#define CAP2     32768
#define FB_CAP   16384

__device__ unsigned int       g_hist[3][NBINS];
__device__ unsigned int       g_pfCnt[3];
__device__ unsigned int       g_cutKey[3];
__device__ unsigned int       g_fbFlag[3];
__device__ unsigned int       g_fbCnt[3];
__device__ unsigned long long g_pf0[CAP0];
__device__ unsigned long long g_pf1[CAP1];
__device__ unsigned long long g_pf2[CAP2];
__device__ unsigned long long g_fb[3][FB_CAP];

// per-level sorted top-1000 (level-major)
__device__ unsigned int g_Lkey[NTOT];     // effkey (post-threshold score key)
__device__ float        g_Lscore[NTOT];
__device__ int          g_Llabel[NTOT];
__device__ float4       g_Lbox[NTOT];

// merged (global sorted order)
__device__ float  g_sScore[NTOT];
__device__ int    g_sLabel[NTOT];
__device__ float4 g_sBox[NTOT];
__device__ float4 g_sShift[NTOT];

__device__ uint4        g_maskV[NTOT * 32];  // 128 words per row
__device__ unsigned int g_suppBits[NW32];    // rows with any suppression bit

// monotone uint key for float ordering, and inverse
__device__ __forceinline__ unsigned int fkey(float x) {
    unsigned int u = __float_as_uint(x);
    return (u & 0x80000000u) ? ~u : (u | 0x80000000u);
}
__device__ __forceinline__ float unkey(unsigned int k) {
    unsigned int u = (k & 0x80000000u) ? (k & 0x7FFFFFFFu) : ~k;
    return __uint_as_float(u);
}

struct Lev { int C, H, W, M, n, logM; float stride; };
__device__ __forceinline__ Lev lev_params(int l) {
    Lev p; p.C = 80;
    if (l == 0)      { p.H = 512; p.W = 512; p.stride = 8.f;  p.logM = 18; }
    else if (l == 1) { p.H = 256; p.W = 256; p.stride = 16.f; p.logM = 16; }
    else             { p.H = 128; p.W = 128; p.stride = 32.f; p.logM = 14; }
    p.M = p.H * p.W; p.n = p.M * p.C;
    return p;
}

__device__ __forceinline__ unsigned int lev_cap(int l) {
    return (l == 0) ? CAP0 : ((l == 1) ? CAP1 : CAP2);
}

// ------------------------------- init --------------------------------------
__global__ void k_init() {
    int t = blockIdx.x * blockDim.x + threadIdx.x;
    int stride = gridDim.x * blockDim.x;
    unsigned int* h = (unsigned int*)g_hist;
    for (int i = t; i < 3 * NBINS; i += stride) h[i] = 0;
    if (t < 3) { g_pfCnt[t] = 0; g_fbCnt[t] = 0; }
    for (int i = t; i < NW32; i += stride) g_suppBits[i] = 0;
    for (int i = t; i < NTOT; i += stride) {
        g_Lkey[i] = 0; g_Lscore[i] = 0.f; g_Llabel[i] = 0;
        g_Lbox[i] = make_float4(0.f, 0.f, 0.f, 0.f);
    }
}

// ---------------- fused histogram + prefilter compaction --------------------
__global__ void k_histpf(const float* __restrict__ c0,
                         const float* __restrict__ c1,
                         const float* __restrict__ c2) {
    int l = blockIdx.y;
    Lev P = lev_params(l);
    const float4* p = (const float4*)(l == 0 ? c0 : (l == 1 ? c1 : c2));
    unsigned long long* pf = (l == 0) ? g_pf0 : ((l == 1) ? g_pf1 : g_pf2);
    unsigned int cap = lev_cap(l);
    int n4 = P.n >> 2;

    __shared__ unsigned int h[NBINS];
    for (int i = threadIdx.x; i < NBINS; i += blockDim.x) h[i] = 0;
    __syncthreads();

    int stride = gridDim.x * blockDim.x;
    int tid = blockIdx.x * blockDim.x + threadIdx.x;
    int lane = threadIdx.x & 31;
    int iters = (n4 + stride - 1) / stride;

    for (int it = 0; it < iters; it++) {
        int i = tid + it * stride;
        bool inb = i < n4;
        float4 v = inb ? p[i] : make_float4(0.f, 0.f, 0.f, 0.f);
        unsigned int kk[4] = { fkey(v.x), fkey(v.y), fkey(v.z), fkey(v.w) };
        if (inb) {
            atomicAdd(&h[kk[0] >> 19], 1u);
            atomicAdd(&h[kk[1] >> 19], 1u);
            atomicAdd(&h[kk[2] >> 19], 1u);
            atomicAdd(&h[kk[3] >> 19], 1u);
        }
#pragma unroll
        for (int e = 0; e < 4; e++) {
            bool take = inb && (kk[e] >= PREKEY);
            unsigned int m = __ballot_sync(0xFFFFFFFFu, take);
            if (take) {
                int leader = __ffs(m) - 1;
                unsigned int pos0 = 0;
                if (lane == leader)
                    pos0 = atomicAdd(&g_pfCnt[l], (unsigned int)__popc(m));
                pos0 = __shfl_sync(m, pos0, leader);
                unsigned int pos = pos0 + __popc(m & ((1u << lane) - 1u));
                if (pos < cap) {
                    int lin = (i << 2) + e;
                    int c = lin >> P.logM;
                    int mm = lin & (P.M - 1);
                    unsigned int flat = (unsigned int)mm * 80u + (unsigned int)c;
                    pf[pos] = ((unsigned long long)kk[e] << 32) |
                              (unsigned long long)(0xFFFFFFFFu - flat);
                }
            }
        }
    }
    __syncthreads();
    for (int i = threadIdx.x; i < NBINS; i += blockDim.x) {
        unsigned int v = h[i];
        if (v) atomicAdd(&g_hist[l][i], v);
    }
}

// ------------------------------ cutoff -------------------------------------
__global__ void k_cutoff() {
    int l = blockIdx.x;
    __shared__ unsigned int chunk[256];
    unsigned int s = 0;
    int base = threadIdx.x * 32;
    for (int r = 0; r < 32; r++) s += g_hist[l][base + r];
    chunk[threadIdx.x] = s;
    __syncthreads();
    if (threadIdx.x == 0) {
        unsigned long long cum = 0;
        int c;
        for (c = 255; c >= 0; c--) {
            if (cum + chunk[c] >= (unsigned long long)NSEL) break;
            cum += chunk[c];
        }
        unsigned int cut = 0;
        if (c >= 0) {
            int b;
            for (b = c * 32 + 31; b >= c * 32; b--) {
                cum += g_hist[l][b];
                if (cum >= (unsigned long long)NSEL) break;
            }
            if (b < c * 32) b = c * 32;
            cut = ((unsigned int)b) << 19;
        }
        g_cutKey[l] = cut;
        g_fbFlag[l] = (cut < PREKEY || g_pfCnt[l] > lev_cap(l)) ? 1u : 0u;
    }
}

// --------------------- fallback full rescan (rare) -------------------------
__global__ void k_fallback(const float* __restrict__ c0,
                           const float* __restrict__ c1,
                           const float* __restrict__ c2) {
    int l = blockIdx.y;
    if (g_fbFlag[l] == 0u) return;
    Lev P = lev_params(l);
    const float4* p = (const float4*)(l == 0 ? c0 : (l == 1 ? c1 : c2));
    unsigned int cut = g_cutKey[l];
    int n4 = P.n >> 2;
    int stride = gridDim.x * blockDim.x;
    int tid = blockIdx.x * blockDim.x + threadIdx.x;
    int lane = threadIdx.x & 31;
    int iters = (n4 + stride - 1) / stride;
    for (int it = 0; it < iters; it++) {
        int i = tid + it * stride;
        bool inb = i < n4;
        float4 v = inb ? p[i] : make_float4(0.f, 0.f, 0.f, 0.f);
        unsigned int kk[4] = { fkey(v.x), fkey(v.y), fkey(v.z), fkey(v.w) };
#pragma unroll
        for (int e = 0; e < 4; e++) {
            bool take = inb && (kk[e] >= cut);
            unsigned int m = __ballot_sync(0xFFFFFFFFu, take);
            if (take) {
                int leader = __ffs(m) - 1;
                unsigned int pos0 = 0;
                if (lane == leader)
                    pos0 = atomicAdd(&g_fbCnt[l], (unsigned int)__popc(m));
                pos0 = __shfl_sync(m, pos0, leader);
                unsigned int pos = pos0 + __popc(m & ((1u << lane) - 1u));
                if (pos < FB_CAP) {
                    int lin = (i << 2) + e;
                    int c = lin >> P.logM;
                    int mm = lin & (P.M - 1);
                    unsigned int flat = (unsigned int)mm * 80u + (unsigned int)c;
                    g_fb[l][pos] = ((unsigned long long)kk[e] << 32) |
                                   (unsigned long long)(0xFFFFFFFFu - flat);
                }
            }
        }
    }
}

// ------------------------------ bitonic ------------------------------------
template <int N>
__device__ __forceinline__ void bitonic_desc(unsigned long long* s) {
    for (int k = 2; k <= N; k <<= 1) {
        for (int j = k >> 1; j > 0; j >>= 1) {
            for (int i = threadIdx.x; i < N; i += blockDim.x) {
                int ixj = i ^ j;
                if (ixj > i) {
                    unsigned long long A = s[i], B = s[ixj];
                    bool descSeg = ((i & k) == 0);
                    if (descSeg ? (A < B) : (A > B)) { s[i] = B; s[ixj] = A; }
                }
            }
            __syncthreads();
        }
    }
}

// ------------- per-level filter + sort + top-1000 + DFL decode -------------
__global__ void __launch_bounds__(1024) k_sortsel(const float* __restrict__ r0,
                                                  const float* __restrict__ r1,
                                                  const float* __restrict__ r2,
                                                  const float* __restrict__ proj) {
    int l = blockIdx.x;
    Lev P = lev_params(l);
    const float* reg = (l == 0 ? r0 : (l == 1 ? r1 : r2));
    __shared__ unsigned long long a[CAND_CAP];
    __shared__ float pw[16];
    __shared__ unsigned int scnt;
    if (threadIdx.x < 16) pw[threadIdx.x] = proj[threadIdx.x];
    if (threadIdx.x == 0) scnt = 0;
    __syncthreads();

    unsigned int cut = g_cutKey[l];
    const unsigned long long* src;
    unsigned int srcN;
    if (g_fbFlag[l]) {
        src = g_fb[l];
        srcN = min(g_fbCnt[l], (unsigned int)FB_CAP);
    } else {
        src = (l == 0) ? g_pf0 : ((l == 1) ? g_pf1 : g_pf2);
        srcN = min(g_pfCnt[l], lev_cap(l));
    }
    for (unsigned int i = threadIdx.x; i < srcN; i += blockDim.x) {
        unsigned long long e = src[i];
        if ((unsigned int)(e >> 32) >= cut) {
            unsigned int pos = atomicAdd(&scnt, 1u);
            if (pos < CAND_CAP) a[pos] = e;
        }
    }
    __syncthreads();
    unsigned int cnt = min(scnt, (unsigned int)CAND_CAP);

    if (cnt <= 2048u) {
        for (int i = threadIdx.x; i < 2048; i += blockDim.x)
            if (i >= (int)cnt) a[i] = 0ULL;
        __syncthreads();
        bitonic_desc<2048>(a);
    } else {
        for (int i = threadIdx.x; i < CAND_CAP; i += blockDim.x)
            if (i >= (int)cnt) a[i] = 0ULL;
        __syncthreads();
        bitonic_desc<CAND_CAP>(a);
    }

    int nsel = (int)cnt < NSEL ? (int)cnt : NSEL;
    int t = threadIdx.x;
    if (t < nsel) {
        unsigned long long e = a[t];
        unsigned int rawkey = (unsigned int)(e >> 32);
        float x = unkey(rawkey);
        unsigned int flat = 0xFFFFFFFFu - (unsigned int)e;
        int m = (int)(flat / 80u);
        int c = (int)(flat % 80u);
        float sc = 1.f / (1.f + expf(-x));
        float eff = (sc > 0.05f) ? sc : 0.f;
        float dist[4];
#pragma unroll
        for (int f = 0; f < 4; f++) {
            float v[16];
            float mx = -1e30f;
#pragma unroll
            for (int r = 0; r < 16; r++) {
                v[r] = reg[(size_t)(f * 16 + r) * (size_t)P.M + (size_t)m];
                mx = fmaxf(mx, v[r]);
            }
            float s = 0.f, d = 0.f;
#pragma unroll
            for (int r = 0; r < 16; r++) {
                float ee = expf(v[r] - mx);
                s += ee;
                d += ee * pw[r];
            }
            dist[f] = d / s;
        }
        int xq = m % P.W;
        int yq = m / P.W;
        float ax = ((float)xq + 0.5f) * P.stride;
        float ay = ((float)yq + 0.5f) * P.stride;
        float4 b = make_float4(ax - dist[0] * P.stride,
                               ay - dist[1] * P.stride,
                               ax + dist[2] * P.stride,
                               ay + dist[3] * P.stride);
        int o = l * NSEL + t;
        g_Lkey[o]   = fkey(eff);
        g_Lscore[o] = eff;
        g_Llabel[o] = c;
        g_Lbox[o]   = b;
    }
}

// -------------------- 3-way merge by rank (stable) -------------------------
// global order: effkey desc; ties -> lower level first, then lower rank.
__global__ void k_merge() {
    int l = blockIdx.x;
    int r = threadIdx.x;
    if (r >= NSEL) return;
    int o = l * NSEL + r;
    unsigned int K = g_Lkey[o];
    int pos = r;
#pragma unroll
    for (int lo = 0; lo < 3; lo++) {
        if (lo == l) continue;
        const unsigned int* arr = &g_Lkey[lo * NSEL];
        int a_ = 0, b_ = NSEL;
        if (lo < l) {   // count entries with K' >= K
            while (a_ < b_) { int mid = (a_ + b_) >> 1; if (arr[mid] >= K) a_ = mid + 1; else b_ = mid; }
        } else {        // count entries with K' > K
            while (a_ < b_) { int mid = (a_ + b_) >> 1; if (arr[mid] >  K) a_ = mid + 1; else b_ = mid; }
        }
        pos += a_;
    }
    float sc = g_Lscore[o];
    int lab  = g_Llabel[o];
    float4 b = g_Lbox[o];
    g_sScore[pos] = sc;
    g_sLabel[pos] = lab;
    g_sBox[pos]   = b;
    float off = (float)lab * 8192.0f;
    g_sShift[pos] = make_float4(b.x + off, b.y + off, b.z + off, b.w + off);
}

// --------------------- suppression bitmask matrix --------------------------
__global__ void __launch_bounds__(256) k_iou() {
    __shared__ float4 sb[NTOT];
    for (int i = threadIdx.x; i < NTOT; i += blockDim.x) sb[i] = g_sShift[i];
    __syncthreads();

    int row  = blockIdx.x * 8 + (threadIdx.x >> 5);
    int lane = threadIdx.x & 31;

    float4 bi = sb[row];
    float ai = (bi.z - bi.x) * (bi.w - bi.y);

    uint4 v = make_uint4(0u, 0u, 0u, 0u);
#pragma unroll
    for (int k = 0; k < NW32; k++) {
        int j = k * 32 + lane;
        bool pred = false;
        if (j < NTOT && j > row) {
            float4 bj = sb[j];
            float aj = (bj.z - bj.x) * (bj.w - bj.y);
            float iw = fminf(bi.z, bj.z) - fmaxf(bi.x, bj.x);
            iw = fmaxf(iw, 0.f);
            float ih = fminf(bi.w, bj.w) - fmaxf(bi.y, bj.y);
            ih = fmaxf(ih, 0.f);
            float inter = iw * ih;
            float iou = inter / (ai + aj - inter + 1e-9f);
            pred = iou > 0.6f;
        }
        unsigned int bal = __ballot_sync(0xFFFFFFFFu, pred);
        if (lane == (k >> 2)) {
            if ((k & 3) == 0)      v.x = bal;
            else if ((k & 3) == 1) v.y = bal;
            else if ((k & 3) == 2) v.z = bal;
            else                   v.w = bal;
        }
    }
    g_maskV[row * 32 + lane] = v;
    unsigned int nz = __ballot_sync(0xFFFFFFFFu, (v.x | v.y | v.z | v.w) != 0u);
    if (lane == 0 && nz)
        atomicOr(&g_suppBits[row >> 5], 1u << (row & 31));
}

// ------------- sparse greedy reduce + output (fused) -----------------------
__global__ void __launch_bounds__(1024, 1) k_reduceout(float* __restrict__ out,
                                                       int out_size) {
    __shared__ unsigned int aliveW[NWPAD];
    __shared__ int list[NTOT];
    __shared__ unsigned int keepW[NW32];

    int t = threadIdx.x, lane = t & 31, w = t >> 5;

    // initial alive bits from scores
#pragma unroll
    for (int pz = 0; pz < 3; pz++) {
        int i = pz * 1024 + t;
        bool al = (i < NTOT) && (g_sScore[i] > 0.f);
        unsigned int bal = __ballot_sync(0xFFFFFFFFu, al);
        if (lane == 0) aliveW[pz * 32 + w] = bal;
    }
    if (t >= NW32 && t < NWPAD) aliveW[t] = 0u;
    __syncthreads();

    if (t < 32) {
        // build ascending list of suppressor rows from g_suppBits
        int total = 0;
#pragma unroll
        for (int pz = 0; pz < 3; pz++) {
            unsigned int wd = g_suppBits[pz * 32 + lane];
            int c = __popc(wd);
            int x = c;
            for (int d = 1; d < 32; d <<= 1) {
                int y = __shfl_up_sync(0xFFFFFFFFu, x, d);
                if (lane >= d) x += y;
            }
            int ex = total + x - c;
            int pt = __shfl_sync(0xFFFFFFFFu, x, 31);
            while (wd) {
                int b = __ffs(wd) - 1;
                list[ex++] = (pz * 32 + lane) * 32 + b;
                wd &= wd - 1;
            }
            total += pt;
        }
        int L = total;   // uniform across lanes
        __syncwarp();

        uint4 A = make_uint4(aliveW[lane * 4 + 0], aliveW[lane * 4 + 1],
                             aliveW[lane * 4 + 2], aliveW[lane * 4 + 3]);

        const uint4* mv = (const uint4*)g_maskV;
        const int PD = 8;
        uint4 buf[PD];
#pragma unroll
        for (int j = 0; j < PD; j++)
            buf[j] = (j < L) ? mv[list[j] * 32 + lane]
                             : make_uint4(0u, 0u, 0u, 0u);

        for (int idx = 0; idx < L; idx++) {
            int i = list[idx];
            unsigned int sel = (unsigned int)(i >> 5) & 3u;
            unsigned int val = (sel == 0) ? A.x : (sel == 1) ? A.y
                              : (sel == 2) ? A.z : A.w;
            unsigned int cur = __shfl_sync(0xFFFFFFFFu, val, i >> 7);
            uint4 Mk = buf[idx & (PD - 1)];
            if ((cur >> (i & 31)) & 1u) {
                A.x &= ~Mk.x; A.y &= ~Mk.y; A.z &= ~Mk.z; A.w &= ~Mk.w;
            }
            int nx = idx + PD;
            buf[idx & (PD - 1)] = (nx < L) ? mv[list[nx] * 32 + lane]
                                           : make_uint4(0u, 0u, 0u, 0u);
        }
#pragma unroll
        for (int q = 0; q < 4; q++) {
            int wi = lane * 4 + q;
            if (wi < NW32)
                keepW[wi] = (q == 0) ? A.x : (q == 1) ? A.y
                           : (q == 2) ? A.z : A.w;
        }
    }
    __syncthreads();

    // outputs: bboxes[3000*4] | scores*keep[3000] | labels[3000] | keep[3000]
    for (int i = t; i < out_size; i += 1024) {
        float v = 0.f;
        if (i < 12000) {
            int r = i >> 2, c = i & 3;
            float4 b = g_sBox[r];
            v = (c == 0) ? b.x : (c == 1) ? b.y : (c == 2) ? b.z : b.w;
        } else if (i < 15000) {
            int j = i - 12000;
            v = ((keepW[j >> 5] >> (j & 31)) & 1u) ? g_sScore[j] : 0.f;
        } else if (i < 18000) {
            v = (float)g_sLabel[i - 15000];
        } else if (i < 21000) {
            int j = i - 18000;
            v = ((keepW[j >> 5] >> (j & 31)) & 1u) ? 1.f : 0.f;
        }
        out[i] = v;
    }
}

// ------------------------------- launch ------------------------------------
extern "C" void kernel_launch(void* const* d_in, const int* in_sizes, int n_in,
                              void* d_out, int out_size) {
    const float* cls0 = (const float*)d_in[0];
    const float* reg0 = (const float*)d_in[1];
    const float* cls1 = (const float*)d_in[2];
    const float* reg1 = (const float*)d_in[3];
    const float* cls2 = (const float*)d_in[4];
    const float* reg2 = (const float*)d_in[5];
    const float* proj = (const float*)d_in[6];
    float* out = (float*)d_out;

    k_init<<<64, 256>>>();
    dim3 g(1024, 3);
    k_histpf<<<g, 256>>>(cls0, cls1, cls2);
    k_cutoff<<<3, 256>>>();
    k_fallback<<<g, 256>>>(cls0, cls1, cls2);
    k_sortsel<<<3, 1024>>>(reg0, reg1, reg2, proj);
    k_merge<<<3, 1024>>>();
    k_iou<<<(NTOT + 7) / 8, 256>>>();
    k_reduceout<<<1, 1024>>>(out, out_size);
}

// round 10
// speedup vs baseline: 12.0233x; 1.0571x over previous
#include <cuda_runtime.h>
#include <math.h>

// ---------------------------------------------------------------------------
// FreeYOLOv2 post-process, v4 (re-run after infra failure):
//   thresholded scan: integer max-tree fast path over 16 elems; only ~0.26%
//   of elements (>2.8 sigma) hit the histogram/candidate slow path (direct
//   global atomics). Exact radix cutoff over the counted tail, full-rescan
//   fallback if cutoff would fall at/below the prefilter bin.
//   Then: per-level bitonic top-1000 + DFL decode, rank-merge, IoU bitmask,
//   sparse greedy reduce fused with output.
// ---------------------------------------------------------------------------

#define NBINS    8192
#define CAND_CAP 4096
#define NSEL     1000
#define NTOT     3000
#define NW32     96
#define NWPAD    128
#define ITHRESH  0x40333333        /* float bits of 2.8f (signed-int compare) */
#define PREKEY   0xC0333333u       /* fkey(2.8f) */
#define CAP0     131072
#define CAP1     65536
#define CAP2     32768
#define FB_CAP   16384

__device__ unsigned int       g_hist[3][NBINS];
__device__ unsigned int       g_pfCnt[3];
__device__ unsigned int       g_cutKey[3];
__device__ unsigned int       g_fbFlag[3];
__device__ unsigned int       g_fbCnt[3];
__device__ unsigned long long g_pf0[CAP0];
__device__ unsigned long long g_pf1[CAP1];
__device__ unsigned long long g_pf2[CAP2];
__device__ unsigned long long g_fb[3][FB_CAP];

// per-level sorted top-1000 (level-major)
__device__ unsigned int g_Lkey[NTOT];
__device__ float        g_Lscore[NTOT];
__device__ int          g_Llabel[NTOT];
__device__ float4       g_Lbox[NTOT];

// merged (global sorted order)
__device__ float  g_sScore[NTOT];
__device__ int    g_sLabel[NTOT];
__device__ float4 g_sBox[NTOT];
__device__ float4 g_sShift[NTOT];

__device__ uint4        g_maskV[NTOT * 32];
__device__ unsigned int g_suppBits[NW32];

__device__ __forceinline__ unsigned int fkey(float x) {
    unsigned int u = __float_as_uint(x);
    return (u & 0x80000000u) ? ~u : (u | 0x80000000u);
}
__device__ __forceinline__ float unkey(unsigned int k) {
    unsigned int u = (k & 0x80000000u) ? (k & 0x7FFFFFFFu) : ~k;
    return __uint_as_float(u);
}

struct Lev { int C, H, W, M, n, logM; float stride; };
__device__ __forceinline__ Lev lev_params(int l) {
    Lev p; p.C = 80;
    if (l == 0)      { p.H = 512; p.W = 512; p.stride = 8.f;  p.logM = 18; }
    else if (l == 1) { p.H = 256; p.W = 256; p.stride = 16.f; p.logM = 16; }
    else             { p.H = 128; p.W = 128; p.stride = 32.f; p.logM = 14; }
    p.M = p.H * p.W; p.n = p.M * p.C;
    return p;
}
__device__ __forceinline__ unsigned int lev_cap(int l) {
    return (l == 0) ? CAP0 : ((l == 1) ? CAP1 : CAP2);
}

// ------------------------------- init --------------------------------------
__global__ void k_init() {
    int t = blockIdx.x * blockDim.x + threadIdx.x;
    int stride = gridDim.x * blockDim.x;
    unsigned int* h = (unsigned int*)g_hist;
    for (int i = t; i < 3 * NBINS; i += stride) h[i] = 0;
    if (t < 3) { g_pfCnt[t] = 0; g_fbCnt[t] = 0; }
    for (int i = t; i < NW32; i += stride) g_suppBits[i] = 0;
    for (int i = t; i < NTOT; i += stride) {
        g_Lkey[i] = 0; g_Lscore[i] = 0.f; g_Llabel[i] = 0;
        g_Lbox[i] = make_float4(0.f, 0.f, 0.f, 0.f);
    }
}

// ------------- thresholded scan: tail histogram + candidates ----------------
__global__ void __launch_bounds__(256) k_scan(const float* __restrict__ c0,
                                              const float* __restrict__ c1,
                                              const float* __restrict__ c2) {
    int l = blockIdx.y;
    Lev P = lev_params(l);
    const int4* p = (const int4*)(l == 0 ? c0 : (l == 1 ? c1 : c2));
    unsigned long long* pf = (l == 0) ? g_pf0 : ((l == 1) ? g_pf1 : g_pf2);
    unsigned int cap = lev_cap(l);
    int n4 = P.n >> 2;
    int stride = gridDim.x * blockDim.x;
    int tid = blockIdx.x * blockDim.x + threadIdx.x;
    const int NEG = (int)0x80000000;

    for (int i0 = tid; i0 < n4; i0 += stride * 4) {
        int idx1 = i0 + stride, idx2 = i0 + 2 * stride, idx3 = i0 + 3 * stride;
        int4 v0 = p[i0];
        int4 v1 = (idx1 < n4) ? p[idx1] : make_int4(NEG, NEG, NEG, NEG);
        int4 v2 = (idx2 < n4) ? p[idx2] : make_int4(NEG, NEG, NEG, NEG);
        int4 v3 = (idx3 < n4) ? p[idx3] : make_int4(NEG, NEG, NEG, NEG);
        int m0 = max(max(v0.x, v0.y), max(v0.z, v0.w));
        int m1 = max(max(v1.x, v1.y), max(v1.z, v1.w));
        int m2 = max(max(v2.x, v2.y), max(v2.z, v2.w));
        int m3 = max(max(v3.x, v3.y), max(v3.z, v3.w));
        int mx = max(max(m0, m1), max(m2, m3));
        if (mx >= ITHRESH) {
            // rare path (~0.26% of elements chip-wide)
            int idxs[4] = { i0, idx1, idx2, idx3 };
            int4 vs[4] = { v0, v1, v2, v3 };
#pragma unroll
            for (int k = 0; k < 4; k++) {
                if (idxs[k] >= n4) continue;
                int comp[4] = { vs[k].x, vs[k].y, vs[k].z, vs[k].w };
#pragma unroll
                for (int e = 0; e < 4; e++) {
                    int b = comp[e];
                    if (b >= ITHRESH) {
                        unsigned int key = ((unsigned int)b) | 0x80000000u;
                        atomicAdd(&g_hist[l][key >> 19], 1u);
                        unsigned int pos = atomicAdd(&g_pfCnt[l], 1u);
                        if (pos < cap) {
                            int lin = (idxs[k] << 2) + e;
                            int c = lin >> P.logM;
                            int mm = lin & (P.M - 1);
                            unsigned int flat =
                                (unsigned int)mm * 80u + (unsigned int)c;
                            pf[pos] = ((unsigned long long)key << 32) |
                                      (unsigned long long)(0xFFFFFFFFu - flat);
                        }
                    }
                }
            }
        }
    }
}

// ------------------------------ cutoff -------------------------------------
__global__ void k_cutoff() {
    int l = blockIdx.x;
    __shared__ unsigned int chunk[256];
    unsigned int s = 0;
    int base = threadIdx.x * 32;
    for (int r = 0; r < 32; r++) s += g_hist[l][base + r];
    chunk[threadIdx.x] = s;
    __syncthreads();
    if (threadIdx.x == 0) {
        unsigned long long cum = 0;
        int c;
        for (c = 255; c >= 0; c--) {
            if (cum + chunk[c] >= (unsigned long long)NSEL) break;
            cum += chunk[c];
        }
        unsigned int cut = 0;
        if (c >= 0) {
            int b;
            for (b = c * 32 + 31; b >= c * 32; b--) {
                cum += g_hist[l][b];
                if (cum >= (unsigned long long)NSEL) break;
            }
            if (b < c * 32) b = c * 32;
            cut = ((unsigned int)b) << 19;
        }
        g_cutKey[l] = cut;
        // hist only counts keys >= PREKEY; the PREKEY bin itself is partial.
        unsigned int prebin = PREKEY >> 19;
        g_fbFlag[l] = ((cut >> 19) <= prebin || g_pfCnt[l] > lev_cap(l)) ? 1u : 0u;
    }
}

// --------------------- fallback full rescan (rare) -------------------------
__global__ void k_fallback(const float* __restrict__ c0,
                           const float* __restrict__ c1,
                           const float* __restrict__ c2) {
    int l = blockIdx.y;
    if (g_fbFlag[l] == 0u) return;
    Lev P = lev_params(l);
    const float4* p = (const float4*)(l == 0 ? c0 : (l == 1 ? c1 : c2));
    unsigned int cut = g_cutKey[l];
    int n4 = P.n >> 2;
    int stride = gridDim.x * blockDim.x;
    int tid = blockIdx.x * blockDim.x + threadIdx.x;
    int lane = threadIdx.x & 31;
    int iters = (n4 + stride - 1) / stride;
    for (int it = 0; it < iters; it++) {
        int i = tid + it * stride;
        bool inb = i < n4;
        float4 v = inb ? p[i] : make_float4(0.f, 0.f, 0.f, 0.f);
        unsigned int kk[4] = { fkey(v.x), fkey(v.y), fkey(v.z), fkey(v.w) };
#pragma unroll
        for (int e = 0; e < 4; e++) {
            bool take = inb && (kk[e] >= cut);
            unsigned int m = __ballot_sync(0xFFFFFFFFu, take);
            if (take) {
                int leader = __ffs(m) - 1;
                unsigned int pos0 = 0;
                if (lane == leader)
                    pos0 = atomicAdd(&g_fbCnt[l], (unsigned int)__popc(m));
                pos0 = __shfl_sync(m, pos0, leader);
                unsigned int pos = pos0 + __popc(m & ((1u << lane) - 1u));
                if (pos < FB_CAP) {
                    int lin = (i << 2) + e;
                    int c = lin >> P.logM;
                    int mm = lin & (P.M - 1);
                    unsigned int flat = (unsigned int)mm * 80u + (unsigned int)c;
                    g_fb[l][pos] = ((unsigned long long)kk[e] << 32) |
                                   (unsigned long long)(0xFFFFFFFFu - flat);
                }
            }
        }
    }
}

// ------------------------------ bitonic ------------------------------------
template <int N>
__device__ __forceinline__ void bitonic_desc(unsigned long long* s) {
    for (int k = 2; k <= N; k <<= 1) {
        for (int j = k >> 1; j > 0; j >>= 1) {
            for (int i = threadIdx.x; i < N; i += blockDim.x) {
                int ixj = i ^ j;
                if (ixj > i) {
                    unsigned long long A = s[i], B = s[ixj];
                    bool descSeg = ((i & k) == 0);
                    if (descSeg ? (A < B) : (A > B)) { s[i] = B; s[ixj] = A; }
                }
            }
            __syncthreads();
        }
    }
}

// ------------- per-level filter + sort + top-1000 + DFL decode -------------
__global__ void __launch_bounds__(1024) k_sortsel(const float* __restrict__ r0,
                                                  const float* __restrict__ r1,
                                                  const float* __restrict__ r2,
                                                  const float* __restrict__ proj) {
    int l = blockIdx.x;
    Lev P = lev_params(l);
    const float* reg = (l == 0 ? r0 : (l == 1 ? r1 : r2));
    __shared__ unsigned long long a[CAND_CAP];
    __shared__ float pw[16];
    __shared__ unsigned int scnt;
    if (threadIdx.x < 16) pw[threadIdx.x] = proj[threadIdx.x];
    if (threadIdx.x == 0) scnt = 0;
    __syncthreads();

    unsigned int cut = g_cutKey[l];
    const unsigned long long* src;
    unsigned int srcN;
    if (g_fbFlag[l]) {
        src = g_fb[l];
        srcN = min(g_fbCnt[l], (unsigned int)FB_CAP);
    } else {
        src = (l == 0) ? g_pf0 : ((l == 1) ? g_pf1 : g_pf2);
        srcN = min(g_pfCnt[l], lev_cap(l));
    }
    for (unsigned int i = threadIdx.x; i < srcN; i += blockDim.x) {
        unsigned long long e = src[i];
        if ((unsigned int)(e >> 32) >= cut) {
            unsigned int pos = atomicAdd(&scnt, 1u);
            if (pos < CAND_CAP) a[pos] = e;
        }
    }
    __syncthreads();
    unsigned int cnt = min(scnt, (unsigned int)CAND_CAP);

    if (cnt <= 2048u) {
        for (int i = threadIdx.x; i < 2048; i += blockDim.x)
            if (i >= (int)cnt) a[i] = 0ULL;
        __syncthreads();
        bitonic_desc<2048>(a);
    } else {
        for (int i = threadIdx.x; i < CAND_CAP; i += blockDim.x)
            if (i >= (int)cnt) a[i] = 0ULL;
        __syncthreads();
        bitonic_desc<CAND_CAP>(a);
    }

    int nsel = (int)cnt < NSEL ? (int)cnt : NSEL;
    int t = threadIdx.x;
    if (t < nsel) {
        unsigned long long e = a[t];
        unsigned int rawkey = (unsigned int)(e >> 32);
        float x = unkey(rawkey);
        unsigned int flat = 0xFFFFFFFFu - (unsigned int)e;
        int m = (int)(flat / 80u);
        int c = (int)(flat % 80u);
        float sc = 1.f / (1.f + expf(-x));
        float eff = (sc > 0.05f) ? sc : 0.f;
        float dist[4];
#pragma unroll
        for (int f = 0; f < 4; f++) {
            float v[16];
            float mx = -1e30f;
#pragma unroll
            for (int r = 0; r < 16; r++) {
                v[r] = reg[(size_t)(f * 16 + r) * (size_t)P.M + (size_t)m];
                mx = fmaxf(mx, v[r]);
            }
            float s = 0.f, d = 0.f;
#pragma unroll
            for (int r = 0; r < 16; r++) {
                float ee = expf(v[r] - mx);
                s += ee;
                d += ee * pw[r];
            }
            dist[f] = d / s;
        }
        int xq = m % P.W;
        int yq = m / P.W;
        float ax = ((float)xq + 0.5f) * P.stride;
        float ay = ((float)yq + 0.5f) * P.stride;
        float4 b = make_float4(ax - dist[0] * P.stride,
                               ay - dist[1] * P.stride,
                               ax + dist[2] * P.stride,
                               ay + dist[3] * P.stride);
        int o = l * NSEL + t;
        g_Lkey[o]   = fkey(eff);
        g_Lscore[o] = eff;
        g_Llabel[o] = c;
        g_Lbox[o]   = b;
    }
}

// -------------------- 3-way merge by rank (stable) -------------------------
__global__ void k_merge() {
    int l = blockIdx.x;
    int r = threadIdx.x;
    if (r >= NSEL) return;
    int o = l * NSEL + r;
    unsigned int K = g_Lkey[o];
    int pos = r;
#pragma unroll
    for (int lo = 0; lo < 3; lo++) {
        if (lo == l) continue;
        const unsigned int* arr = &g_Lkey[lo * NSEL];
        int a_ = 0, b_ = NSEL;
        if (lo < l) {
            while (a_ < b_) { int mid = (a_ + b_) >> 1; if (arr[mid] >= K) a_ = mid + 1; else b_ = mid; }
        } else {
            while (a_ < b_) { int mid = (a_ + b_) >> 1; if (arr[mid] >  K) a_ = mid + 1; else b_ = mid; }
        }
        pos += a_;
    }
    float sc = g_Lscore[o];
    int lab  = g_Llabel[o];
    float4 b = g_Lbox[o];
    g_sScore[pos] = sc;
    g_sLabel[pos] = lab;
    g_sBox[pos]   = b;
    float off = (float)lab * 8192.0f;
    g_sShift[pos] = make_float4(b.x + off, b.y + off, b.z + off, b.w + off);
}

// --------------------- suppression bitmask matrix --------------------------
__global__ void __launch_bounds__(256) k_iou() {
    __shared__ float4 sb[NTOT];
    for (int i = threadIdx.x; i < NTOT; i += blockDim.x) sb[i] = g_sShift[i];
    __syncthreads();

    int row  = blockIdx.x * 8 + (threadIdx.x >> 5);
    int lane = threadIdx.x & 31;

    float4 bi = sb[row];
    float ai = (bi.z - bi.x) * (bi.w - bi.y);

    uint4 v = make_uint4(0u, 0u, 0u, 0u);
#pragma unroll
    for (int k = 0; k < NW32; k++) {
        int j = k * 32 + lane;
        bool pred = false;
        if (j < NTOT && j > row) {
            float4 bj = sb[j];
            float aj = (bj.z - bj.x) * (bj.w - bj.y);
            float iw = fminf(bi.z, bj.z) - fmaxf(bi.x, bj.x);
            iw = fmaxf(iw, 0.f);
            float ih = fminf(bi.w, bj.w) - fmaxf(bi.y, bj.y);
            ih = fmaxf(ih, 0.f);
            float inter = iw * ih;
            float iou = inter / (ai + aj - inter + 1e-9f);
            pred = iou > 0.6f;
        }
        unsigned int bal = __ballot_sync(0xFFFFFFFFu, pred);
        if (lane == (k >> 2)) {
            if ((k & 3) == 0)      v.x = bal;
            else if ((k & 3) == 1) v.y = bal;
            else if ((k & 3) == 2) v.z = bal;
            else                   v.w = bal;
        }
    }
    g_maskV[row * 32 + lane] = v;
    unsigned int nz = __ballot_sync(0xFFFFFFFFu, (v.x | v.y | v.z | v.w) != 0u);
    if (lane == 0 && nz)
        atomicOr(&g_suppBits[row >> 5], 1u << (row & 31));
}

// ------------- sparse greedy reduce + output (fused) -----------------------
__global__ void __launch_bounds__(1024, 1) k_reduceout(float* __restrict__ out,
                                                       int out_size) {
    __shared__ unsigned int aliveW[NWPAD];
    __shared__ int list[NTOT];
    __shared__ unsigned int keepW[NW32];

    int t = threadIdx.x, lane = t & 31, w = t >> 5;

#pragma unroll
    for (int pz = 0; pz < 3; pz++) {
        int i = pz * 1024 + t;
        bool al = (i < NTOT) && (g_sScore[i] > 0.f);
        unsigned int bal = __ballot_sync(0xFFFFFFFFu, al);
        if (lane == 0) aliveW[pz * 32 + w] = bal;
    }
    if (t >= NW32 && t < NWPAD) aliveW[t] = 0u;
    __syncthreads();

    if (t < 32) {
        int total = 0;
#pragma unroll
        for (int pz = 0; pz < 3; pz++) {
            unsigned int wd = g_suppBits[pz * 32 + lane];
            int c = __popc(wd);
            int x = c;
            for (int d = 1; d < 32; d <<= 1) {
                int y = __shfl_up_sync(0xFFFFFFFFu, x, d);
                if (lane >= d) x += y;
            }
            int ex = total + x - c;
            int pt = __shfl_sync(0xFFFFFFFFu, x, 31);
            while (wd) {
                int b = __ffs(wd) - 1;
                list[ex++] = (pz * 32 + lane) * 32 + b;
                wd &= wd - 1;
            }
            total += pt;
        }
        int L = total;
        __syncwarp();

        uint4 A = make_uint4(aliveW[lane * 4 + 0], aliveW[lane * 4 + 1],
                             aliveW[lane * 4 + 2], aliveW[lane * 4 + 3]);

        const uint4* mv = (const uint4*)g_maskV;
        const int PD = 8;
        uint4 buf[PD];
#pragma unroll
        for (int j = 0; j < PD; j++)
            buf[j] = (j < L) ? mv[list[j] * 32 + lane]
                             : make_uint4(0u, 0u, 0u, 0u);

        for (int idx = 0; idx < L; idx++) {
            int i = list[idx];
            unsigned int sel = (unsigned int)(i >> 5) & 3u;
            unsigned int val = (sel == 0) ? A.x : (sel == 1) ? A.y
                              : (sel == 2) ? A.z : A.w;
            unsigned int cur = __shfl_sync(0xFFFFFFFFu, val, i >> 7);
            uint4 Mk = buf[idx & (PD - 1)];
            if ((cur >> (i & 31)) & 1u) {
                A.x &= ~Mk.x; A.y &= ~Mk.y; A.z &= ~Mk.z; A.w &= ~Mk.w;
            }
            int nx = idx + PD;
            buf[idx & (PD - 1)] = (nx < L) ? mv[list[nx] * 32 + lane]
                                           : make_uint4(0u, 0u, 0u, 0u);
        }
#pragma unroll
        for (int q = 0; q < 4; q++) {
            int wi = lane * 4 + q;
            if (wi < NW32)
                keepW[wi] = (q == 0) ? A.x : (q == 1) ? A.y
                           : (q == 2) ? A.z : A.w;
        }
    }
    __syncthreads();

    for (int i = t; i < out_size; i += 1024) {
        float v = 0.f;
        if (i < 12000) {
            int r = i >> 2, c = i & 3;
            float4 b = g_sBox[r];
            v = (c == 0) ? b.x : (c == 1) ? b.y : (c == 2) ? b.z : b.w;
        } else if (i < 15000) {
            int j = i - 12000;
            v = ((keepW[j >> 5] >> (j & 31)) & 1u) ? g_sScore[j] : 0.f;
        } else if (i < 18000) {
            v = (float)g_sLabel[i - 15000];
        } else if (i < 21000) {
            int j = i - 18000;
            v = ((keepW[j >> 5] >> (j & 31)) & 1u) ? 1.f : 0.f;
        }
        out[i] = v;
    }
}

// ------------------------------- launch ------------------------------------
extern "C" void kernel_launch(void* const* d_in, const int* in_sizes, int n_in,
                              void* d_out, int out_size) {
    const float* cls0 = (const float*)d_in[0];
    const float* reg0 = (const float*)d_in[1];
    const float* cls1 = (const float*)d_in[2];
    const float* reg1 = (const float*)d_in[3];
    const float* cls2 = (const float*)d_in[4];
    const float* reg2 = (const float*)d_in[5];
    const float* proj = (const float*)d_in[6];
    float* out = (float*)d_out;

    k_init<<<32, 256>>>();
    dim3 g(1024, 3);
    k_scan<<<g, 256>>>(cls0, cls1, cls2);
    k_cutoff<<<3, 256>>>();
    dim3 gf(256, 3);
    k_fallback<<<gf, 256>>>(cls0, cls1, cls2);
    k_sortsel<<<3, 1024>>>(reg0, reg1, reg2, proj);
    k_merge<<<3, 1024>>>();
    k_iou<<<(NTOT + 7) / 8, 256>>>();
    k_reduceout<<<1, 1024>>>(out, out_size);
}